// round 2
// baseline (speedup 1.0000x reference)
#include <cuda_runtime.h>
#include <cuda_bf16.h>
#include <math.h>

#define BATCH   4
#define NNODES  4096
#define DIM     64
#define DEPTH   3

#define BM 64
#define BN 64
#define BK 32
#define GEMM_THREADS 256

// ---------------- scratch (device globals; no allocation allowed) ----------------
__device__ float g_deg[BATCH * NNODES];                 // d vector
__device__ float g_zA [BATCH * NNODES * DIM];           // scaled-h ping
__device__ float g_zB [BATCH * NNODES * DIM];           // scaled-h pong
__device__ float g_h1 [BATCH * NNODES * DIM];
__device__ float g_h2 [BATCH * NNODES * DIM];
__device__ float g_h3 [BATCH * NNODES * DIM];

// ---------------- cp.async helpers ----------------
__device__ __forceinline__ void cp_async16(void* smem_dst, const void* gmem_src) {
    unsigned s = (unsigned)__cvta_generic_to_shared(smem_dst);
    asm volatile("cp.async.cg.shared.global [%0], [%1], 16;\n" :: "r"(s), "l"(gmem_src));
}
__device__ __forceinline__ void cp_commit() {
    asm volatile("cp.async.commit_group;\n");
}
template<int NREM>
__device__ __forceinline__ void cp_wait() {
    asm volatile("cp.async.wait_group %0;\n" :: "n"(NREM));
}

// ---------------- 1) degrees: d[b,i] = 1/(sqrt(1 + sum_j G[b,i,j]) + 1e-7) ----------------
__global__ void degree_kernel(const float* __restrict__ graph, float* __restrict__ dvec) {
    const int row = blockIdx.x;                 // b*N + i
    const float4* g4 = (const float4*)(graph + (size_t)row * NNODES);
    float s = 0.f;
    #pragma unroll
    for (int k = 0; k < NNODES / 4 / 256; k++) {
        float4 v = g4[threadIdx.x + k * 256];
        s += (v.x + v.y) + (v.z + v.w);
    }
    // warp reduce
    #pragma unroll
    for (int o = 16; o > 0; o >>= 1) s += __shfl_down_sync(0xffffffffu, s, o);
    __shared__ float red[8];
    if ((threadIdx.x & 31) == 0) red[threadIdx.x >> 5] = s;
    __syncthreads();
    if (threadIdx.x == 0) {
        float tot = 1.0f;   // +I self loop contributes 1 to the row sum
        #pragma unroll
        for (int w = 0; w < 8; w++) tot += red[w];
        dvec[row] = 1.0f / (sqrtf(tot) + 1e-7f);
    }
}

// ---------------- 2) z0 = D * x ----------------
__global__ void scale_x_kernel(const float* __restrict__ x, const float* __restrict__ dvec,
                               float* __restrict__ z) {
    int idx = blockIdx.x * blockDim.x + threadIdx.x;     // float4 index, total = B*N*DIM/4
    float4 v = ((const float4*)x)[idx];
    float d = dvec[idx >> 4];                            // 16 float4 per node row
    v.x *= d; v.y *= d; v.z *= d; v.w *= d;
    ((float4*)z)[idx] = v;
}

// ---------------- 3) propagation GEMM: acc = graph @ z ;
//      h = d_i * (acc + z_i)   (identity term),  z_out = d_i * h ----------------
__global__ void __launch_bounds__(GEMM_THREADS, 2)
prop_gemm_kernel(const float* __restrict__ graph,
                 const float* __restrict__ z_in,
                 const float* __restrict__ dvec,
                 float* __restrict__ h_out,
                 float* __restrict__ z_out)
{
    const int b = blockIdx.z;
    const int rowBase = blockIdx.x * BM;
    const float* G = graph + (size_t)b * NNODES * NNODES;
    const float* Z = z_in  + (size_t)b * NNODES * DIM;
    const float* D = g_deg + (size_t)b * NNODES;   (void)dvec;

    __shared__ float As[2][BM][36];   // padded stride 36: 16B aligned, conflict-light
    __shared__ float Bs[2][BK][BN];

    const int tid = threadIdx.x;
    const int tx  = tid & 15;         // n group (0..15)
    const int ty  = tid >> 4;         // m group (0..15)
    const int m0  = ty * 4;
    const int n0  = tx * 4;

    float acc[4][4];
    #pragma unroll
    for (int r = 0; r < 4; r++)
        #pragma unroll
        for (int s = 0; s < 4; s++) acc[r][s] = 0.f;

    const int NT = NNODES / BK;       // 128 k-tiles

    // ---- tile issue (A: 64x32, B: 32x64; both pure copies) ----
    auto issue = [&](int t, int st) {
        const int k0 = t * BK;
        #pragma unroll
        for (int u = 0; u < 2; u++) {
            int i  = tid + u * 256;       // 0..511 float4 of A
            int m  = i >> 3;              // 8 float4 per A row
            int k4 = i & 7;
            cp_async16(&As[st][m][k4 * 4],
                       G + (size_t)(rowBase + m) * NNODES + k0 + k4 * 4);
        }
        #pragma unroll
        for (int u = 0; u < 2; u++) {
            int i  = tid + u * 256;       // 0..511 float4 of B
            int k  = i >> 4;              // 16 float4 per B row
            int n4 = i & 15;
            cp_async16(&Bs[st][k][n4 * 4],
                       Z + (size_t)(k0 + k) * DIM + n4 * 4);
        }
    };

    issue(0, 0);
    cp_commit();

    for (int t = 0; t < NT; t++) {
        const int st = t & 1;
        if (t + 1 < NT) {
            issue(t + 1, st ^ 1);
            cp_commit();
            cp_wait<1>();   // oldest (current tile) done
        } else {
            cp_wait<0>();
        }
        __syncthreads();

        #pragma unroll
        for (int k = 0; k < BK; k++) {
            float a0 = As[st][m0 + 0][k];
            float a1 = As[st][m0 + 1][k];
            float a2 = As[st][m0 + 2][k];
            float a3 = As[st][m0 + 3][k];
            float4 bv = *(const float4*)&Bs[st][k][n0];
            acc[0][0] += a0 * bv.x; acc[0][1] += a0 * bv.y; acc[0][2] += a0 * bv.z; acc[0][3] += a0 * bv.w;
            acc[1][0] += a1 * bv.x; acc[1][1] += a1 * bv.y; acc[1][2] += a1 * bv.z; acc[1][3] += a1 * bv.w;
            acc[2][0] += a2 * bv.x; acc[2][1] += a2 * bv.y; acc[2][2] += a2 * bv.z; acc[2][3] += a2 * bv.w;
            acc[3][0] += a3 * bv.x; acc[3][1] += a3 * bv.y; acc[3][2] += a3 * bv.z; acc[3][3] += a3 * bv.w;
        }
        __syncthreads();
    }

    // epilogue: + identity in z-space, scale by d_i; emit h and z_next
    float* H  = h_out + (size_t)b * NNODES * DIM;
    float* ZO = z_out + (size_t)b * NNODES * DIM;
    #pragma unroll
    for (int r = 0; r < 4; r++) {
        const int gi = rowBase + m0 + r;
        const float di = D[gi];
        float4 zv = *(const float4*)&Z[(size_t)gi * DIM + n0];
        float4 hv, zo;
        hv.x = di * (acc[r][0] + zv.x);
        hv.y = di * (acc[r][1] + zv.y);
        hv.z = di * (acc[r][2] + zv.z);
        hv.w = di * (acc[r][3] + zv.w);
        zo.x = di * hv.x; zo.y = di * hv.y; zo.z = di * hv.z; zo.w = di * hv.w;
        *(float4*)&H [(size_t)gi * DIM + n0] = hv;
        *(float4*)&ZO[(size_t)gi * DIM + n0] = zo;
    }
}

// ---------------- 4) out = concat(x,h1,h2,h3) @ W^T + b ----------------
// rows = B*N = 16384, features = 256, outputs = 64
__global__ void __launch_bounds__(256)
out_gemm_kernel(const float* __restrict__ x,
                const float* __restrict__ h1,
                const float* __restrict__ h2,
                const float* __restrict__ h3,
                const float* __restrict__ W,     // [64][256]
                const float* __restrict__ bias,  // [64]
                float* __restrict__ out)
{
    __shared__ float catS[16][256];
    __shared__ float Wt[64][65];      // transposed W chunk: Wt[f_local][o]

    const int tid = threadIdx.x;
    const int rowBase = blockIdx.x * 16;

    // stage cat rows (4 sources x 64 floats per row)
    const float* srcs[4] = { x, h1, h2, h3 };
    {
        int r = tid >> 4, f4 = tid & 15;
        #pragma unroll
        for (int s = 0; s < 4; s++) {
            float4 v = *(const float4*)&srcs[s][(size_t)(rowBase + r) * DIM + f4 * 4];
            *(float4*)&catS[r][s * 64 + f4 * 4] = v;
        }
    }

    const int o  = tid & 63;          // output column
    const int rg = tid >> 6;          // 0..3 row group

    float acc[4];
    {
        float bv = bias[o];
        #pragma unroll
        for (int j = 0; j < 4; j++) acc[j] = bv;
    }

    for (int fc = 0; fc < 4; fc++) {
        __syncthreads();
        // load W[:, fc*64 .. fc*64+63] transposed into Wt
        #pragma unroll
        for (int u = 0; u < 4; u++) {
            int i  = tid + u * 256;   // 0..1023 float4 of the 64x64 chunk
            int ro = i >> 4;
            int f4 = i & 15;
            float4 v = *(const float4*)&W[(size_t)ro * 256 + fc * 64 + f4 * 4];
            Wt[f4 * 4 + 0][ro] = v.x;
            Wt[f4 * 4 + 1][ro] = v.y;
            Wt[f4 * 4 + 2][ro] = v.z;
            Wt[f4 * 4 + 3][ro] = v.w;
        }
        __syncthreads();
        #pragma unroll
        for (int fl = 0; fl < 64; fl++) {
            float w = Wt[fl][o];
            #pragma unroll
            for (int j = 0; j < 4; j++)
                acc[j] += catS[rg * 4 + j][fc * 64 + fl] * w;
        }
    }

    #pragma unroll
    for (int j = 0; j < 4; j++)
        out[(size_t)(rowBase + rg * 4 + j) * DIM + o] = acc[j];
}

// ---------------- launch ----------------
static float* symAddr(const void* symbol) {
    void* p = nullptr;
    cudaGetSymbolAddress(&p, symbol);
    return (float*)p;
}

extern "C" void kernel_launch(void* const* d_in, const int* in_sizes, int n_in,
                              void* d_out, int out_size) {
    const float* x     = (const float*)d_in[0];   // [4,4096,64]
    const float* graph = (const float*)d_in[1];   // [4,4096,4096]
    const float* W     = (const float*)d_in[2];   // [64,256]
    const float* bias  = (const float*)d_in[3];   // [64]
    float* out = (float*)d_out;                   // [4,4096,64]

    float* deg = symAddr(g_deg);
    float* zA  = symAddr(g_zA);
    float* zB  = symAddr(g_zB);
    float* h1  = symAddr(g_h1);
    float* h2  = symAddr(g_h2);
    float* h3  = symAddr(g_h3);

    // 1) degrees
    degree_kernel<<<BATCH * NNODES, 256>>>(graph, deg);

    // 2) z0 = D x
    scale_x_kernel<<<(BATCH * NNODES * DIM / 4) / 256, 256>>>(x, deg, zA);

    // 3) three propagation GEMMs
    dim3 gg(NNODES / BM, 1, BATCH);
    prop_gemm_kernel<<<gg, GEMM_THREADS>>>(graph, zA, deg, h1, zB);
    prop_gemm_kernel<<<gg, GEMM_THREADS>>>(graph, zB, deg, h2, zA);
    prop_gemm_kernel<<<gg, GEMM_THREADS>>>(graph, zA, deg, h3, zB);

    // 4) output projection
    out_gemm_kernel<<<(BATCH * NNODES) / 16, 256>>>(x, h1, h2, h3, W, bias, out);
}

// round 3
// speedup vs baseline: 1.0547x; 1.0547x over previous
#include <cuda_runtime.h>
#include <cuda_bf16.h>
#include <math.h>

#define BATCH   4
#define NNODES  4096
#define DIM     64
#define DEPTH   3

#define BM 64
#define BN 64
#define BK 32
#define GEMM_THREADS 256

// ---------------- scratch (device globals; no allocation allowed) ----------------
__device__ float g_deg[BATCH * NNODES];                 // d vector
__device__ float g_zA [BATCH * NNODES * DIM];           // scaled-h ping
__device__ float g_zB [BATCH * NNODES * DIM];           // scaled-h pong
__device__ float g_h1 [BATCH * NNODES * DIM];
__device__ float g_h2 [BATCH * NNODES * DIM];
__device__ float g_h3 [BATCH * NNODES * DIM];

// ---------------- cp.async helpers ----------------
__device__ __forceinline__ void cp_async16(void* smem_dst, const void* gmem_src) {
    unsigned s = (unsigned)__cvta_generic_to_shared(smem_dst);
    asm volatile("cp.async.cg.shared.global [%0], [%1], 16;\n" :: "r"(s), "l"(gmem_src));
}
__device__ __forceinline__ void cp_commit() {
    asm volatile("cp.async.commit_group;\n");
}
template<int NREM>
__device__ __forceinline__ void cp_wait() {
    asm volatile("cp.async.wait_group %0;\n" :: "n"(NREM));
}

// ---------------- 1) degrees: d[b,i] = 1/(sqrt(1 + sum_j G[b,i,j]) + 1e-7) ----------------
__global__ void degree_kernel(const float* __restrict__ graph, float* __restrict__ dvec) {
    const int row = blockIdx.x;                 // b*N + i
    const float4* g4 = (const float4*)(graph + (size_t)row * NNODES);
    float s = 0.f;
    #pragma unroll
    for (int k = 0; k < NNODES / 4 / 256; k++) {
        float4 v = g4[threadIdx.x + k * 256];
        s += (v.x + v.y) + (v.z + v.w);
    }
    // warp reduce
    #pragma unroll
    for (int o = 16; o > 0; o >>= 1) s += __shfl_down_sync(0xffffffffu, s, o);
    __shared__ float red[8];
    if ((threadIdx.x & 31) == 0) red[threadIdx.x >> 5] = s;
    __syncthreads();
    if (threadIdx.x == 0) {
        float tot = 1.0f;   // +I self loop contributes 1 to the row sum
        #pragma unroll
        for (int w = 0; w < 8; w++) tot += red[w];
        dvec[row] = 1.0f / (sqrtf(tot) + 1e-7f);
    }
}

// ---------------- 2) z0 = D * x ----------------
__global__ void scale_x_kernel(const float* __restrict__ x, const float* __restrict__ dvec,
                               float* __restrict__ z) {
    int idx = blockIdx.x * blockDim.x + threadIdx.x;     // float4 index, total = B*N*DIM/4
    float4 v = ((const float4*)x)[idx];
    float d = dvec[idx >> 4];                            // 16 float4 per node row
    v.x *= d; v.y *= d; v.z *= d; v.w *= d;
    ((float4*)z)[idx] = v;
}

// ---------------- 3) propagation GEMM: acc = graph @ z ;
//      h = d_i * (acc + z_i)   (identity term),  z_out = d_i * h ----------------
__global__ void __launch_bounds__(GEMM_THREADS, 2)
prop_gemm_kernel(const float* __restrict__ graph,
                 const float* __restrict__ z_in,
                 const float* __restrict__ dvec,
                 float* __restrict__ h_out,
                 float* __restrict__ z_out)
{
    const int b = blockIdx.z;
    const int rowBase = blockIdx.x * BM;
    const float* G = graph + (size_t)b * NNODES * NNODES;
    const float* Z = z_in  + (size_t)b * NNODES * DIM;
    const float* D = g_deg + (size_t)b * NNODES;   (void)dvec;

    __shared__ float As[2][BM][36];   // padded stride 36: 16B aligned, conflict-light
    __shared__ float Bs[2][BK][BN];

    const int tid = threadIdx.x;
    const int tx  = tid & 15;         // n group (0..15)
    const int ty  = tid >> 4;         // m group (0..15)
    const int m0  = ty * 4;
    const int n0  = tx * 4;

    float acc[4][4];
    #pragma unroll
    for (int r = 0; r < 4; r++)
        #pragma unroll
        for (int s = 0; s < 4; s++) acc[r][s] = 0.f;

    const int NT = NNODES / BK;       // 128 k-tiles

    // ---- tile issue (A: 64x32, B: 32x64; both pure copies) ----
    auto issue = [&](int t, int st) {
        const int k0 = t * BK;
        #pragma unroll
        for (int u = 0; u < 2; u++) {
            int i  = tid + u * 256;       // 0..511 float4 of A
            int m  = i >> 3;              // 8 float4 per A row
            int k4 = i & 7;
            cp_async16(&As[st][m][k4 * 4],
                       G + (size_t)(rowBase + m) * NNODES + k0 + k4 * 4);
        }
        #pragma unroll
        for (int u = 0; u < 2; u++) {
            int i  = tid + u * 256;       // 0..511 float4 of B
            int k  = i >> 4;              // 16 float4 per B row
            int n4 = i & 15;
            cp_async16(&Bs[st][k][n4 * 4],
                       Z + (size_t)(k0 + k) * DIM + n4 * 4);
        }
    };

    issue(0, 0);
    cp_commit();

    for (int t = 0; t < NT; t++) {
        const int st = t & 1;
        if (t + 1 < NT) {
            issue(t + 1, st ^ 1);
            cp_commit();
            cp_wait<1>();   // oldest (current tile) done
        } else {
            cp_wait<0>();
        }
        __syncthreads();

        #pragma unroll
        for (int k = 0; k < BK; k++) {
            float a0 = As[st][m0 + 0][k];
            float a1 = As[st][m0 + 1][k];
            float a2 = As[st][m0 + 2][k];
            float a3 = As[st][m0 + 3][k];
            float4 bv = *(const float4*)&Bs[st][k][n0];
            acc[0][0] += a0 * bv.x; acc[0][1] += a0 * bv.y; acc[0][2] += a0 * bv.z; acc[0][3] += a0 * bv.w;
            acc[1][0] += a1 * bv.x; acc[1][1] += a1 * bv.y; acc[1][2] += a1 * bv.z; acc[1][3] += a1 * bv.w;
            acc[2][0] += a2 * bv.x; acc[2][1] += a2 * bv.y; acc[2][2] += a2 * bv.z; acc[2][3] += a2 * bv.w;
            acc[3][0] += a3 * bv.x; acc[3][1] += a3 * bv.y; acc[3][2] += a3 * bv.z; acc[3][3] += a3 * bv.w;
        }
        __syncthreads();
    }

    // epilogue: + identity in z-space, scale by d_i; emit h and z_next
    float* H  = h_out + (size_t)b * NNODES * DIM;
    float* ZO = z_out + (size_t)b * NNODES * DIM;
    #pragma unroll
    for (int r = 0; r < 4; r++) {
        const int gi = rowBase + m0 + r;
        const float di = D[gi];
        float4 zv = *(const float4*)&Z[(size_t)gi * DIM + n0];
        float4 hv, zo;
        hv.x = di * (acc[r][0] + zv.x);
        hv.y = di * (acc[r][1] + zv.y);
        hv.z = di * (acc[r][2] + zv.z);
        hv.w = di * (acc[r][3] + zv.w);
        zo.x = di * hv.x; zo.y = di * hv.y; zo.z = di * hv.z; zo.w = di * hv.w;
        *(float4*)&H [(size_t)gi * DIM + n0] = hv;
        *(float4*)&ZO[(size_t)gi * DIM + n0] = zo;
    }
}

// ---------------- 4) out = concat(x,h1,h2,h3) @ W^T + b ----------------
// rows = B*N = 16384, features = 256, outputs = 64
__global__ void __launch_bounds__(256)
out_gemm_kernel(const float* __restrict__ x,
                const float* __restrict__ h1,
                const float* __restrict__ h2,
                const float* __restrict__ h3,
                const float* __restrict__ W,     // [64][256]
                const float* __restrict__ bias,  // [64]
                float* __restrict__ out)
{
    __shared__ float catS[16][256];
    __shared__ float Wt[64][65];      // transposed W chunk: Wt[f_local][o]

    const int tid = threadIdx.x;
    const int rowBase = blockIdx.x * 16;

    // stage cat rows (4 sources x 64 floats per row)
    const float* srcs[4] = { x, h1, h2, h3 };
    {
        int r = tid >> 4, f4 = tid & 15;
        #pragma unroll
        for (int s = 0; s < 4; s++) {
            float4 v = *(const float4*)&srcs[s][(size_t)(rowBase + r) * DIM + f4 * 4];
            *(float4*)&catS[r][s * 64 + f4 * 4] = v;
        }
    }

    const int o  = tid & 63;          // output column
    const int rg = tid >> 6;          // 0..3 row group

    float acc[4];
    {
        float bv = bias[o];
        #pragma unroll
        for (int j = 0; j < 4; j++) acc[j] = bv;
    }

    for (int fc = 0; fc < 4; fc++) {
        __syncthreads();
        // load W[:, fc*64 .. fc*64+63] transposed into Wt
        #pragma unroll
        for (int u = 0; u < 4; u++) {
            int i  = tid + u * 256;   // 0..1023 float4 of the 64x64 chunk
            int ro = i >> 4;
            int f4 = i & 15;
            float4 v = *(const float4*)&W[(size_t)ro * 256 + fc * 64 + f4 * 4];
            Wt[f4 * 4 + 0][ro] = v.x;
            Wt[f4 * 4 + 1][ro] = v.y;
            Wt[f4 * 4 + 2][ro] = v.z;
            Wt[f4 * 4 + 3][ro] = v.w;
        }
        __syncthreads();
        #pragma unroll
        for (int fl = 0; fl < 64; fl++) {
            float w = Wt[fl][o];
            #pragma unroll
            for (int j = 0; j < 4; j++)
                acc[j] += catS[rg * 4 + j][fc * 64 + fl] * w;
        }
    }

    #pragma unroll
    for (int j = 0; j < 4; j++)
        out[(size_t)(rowBase + rg * 4 + j) * DIM + o] = acc[j];
}

// ---------------- launch ----------------
static float* symAddr(const void* symbol) {
    void* p = nullptr;
    cudaGetSymbolAddress(&p, symbol);
    return (float*)p;
}

extern "C" void kernel_launch(void* const* d_in, const int* in_sizes, int n_in,
                              void* d_out, int out_size) {
    const float* x     = (const float*)d_in[0];   // [4,4096,64]
    const float* graph = (const float*)d_in[1];   // [4,4096,4096]
    const float* W     = (const float*)d_in[2];   // [64,256]
    const float* bias  = (const float*)d_in[3];   // [64]
    float* out = (float*)d_out;                   // [4,4096,64]

    float* deg = symAddr(g_deg);
    float* zA  = symAddr(g_zA);
    float* zB  = symAddr(g_zB);
    float* h1  = symAddr(g_h1);
    float* h2  = symAddr(g_h2);
    float* h3  = symAddr(g_h3);

    // 1) degrees
    degree_kernel<<<BATCH * NNODES, 256>>>(graph, deg);

    // 2) z0 = D x
    scale_x_kernel<<<(BATCH * NNODES * DIM / 4) / 256, 256>>>(x, deg, zA);

    // 3) three propagation GEMMs
    dim3 gg(NNODES / BM, 1, BATCH);
    prop_gemm_kernel<<<gg, GEMM_THREADS>>>(graph, zA, deg, h1, zB);
    prop_gemm_kernel<<<gg, GEMM_THREADS>>>(graph, zB, deg, h2, zA);
    prop_gemm_kernel<<<gg, GEMM_THREADS>>>(graph, zA, deg, h3, zB);

    // 4) output projection
    out_gemm_kernel<<<(BATCH * NNODES) / 16, 256>>>(x, h1, h2, h3, W, bias, out);
}